// round 12
// baseline (speedup 1.0000x reference)
#include <cuda_runtime.h>

#define NOUT 48
#define CIN 384
#define NPIX 35200       // 200*176; %32==0, %8==0
#define NB 4
#define TOTAL_PIX 140800 // = 550 * 256
#define NSTAGE 48        // CIN / 8
#define RING 8           // ring depth; prefetch distance 7

#define SA_ROW 40        // 32 px + pad; 40 mod 32 = 8 -> A-frag LDS conflict-free
#define SA_BUF (8 * SA_ROW)          // 320 floats per stage buffer
#define SA_WARP (RING * SA_BUF)      // 2560 floats per warp
#define SMEM_FLOATS (8 * SA_WARP)    // 20480 -> 81920 B

extern __shared__ float s_buf[];

__device__ __forceinline__ float to_tf32(float x) {
    float r;
    asm("cvt.rna.tf32.f32 %0, %1;" : "=f"(r) : "f"(x));
    return r;
}

__device__ __forceinline__ void mma_tf32(float c[4], const unsigned a[4], const unsigned b[2]) {
    asm("mma.sync.aligned.m16n8k8.row.col.f32.tf32.tf32.f32 "
        "{%0,%1,%2,%3}, {%4,%5,%6,%7}, {%8,%9}, {%0,%1,%2,%3};"
        : "+f"(c[0]), "+f"(c[1]), "+f"(c[2]), "+f"(c[3])
        : "r"(a[0]), "r"(a[1]), "r"(a[2]), "r"(a[3]), "r"(b[0]), "r"(b[1]));
}

// cp.async.cg: L1-bypass (keeps L1 for the weight stream). "memory" clobbers keep
// the compiler from moving fragment LDS across pipeline ops.
__device__ __forceinline__ void cp16(unsigned sdst, const float* gsrc) {
    asm volatile("cp.async.cg.shared.global [%0], [%1], 16;\n"
                 :: "r"(sdst), "l"(gsrc) : "memory");
}
__device__ __forceinline__ void cp_commit() {
    asm volatile("cp.async.commit_group;\n" ::: "memory");
}
template <int N>
__device__ __forceinline__ void cp_wait() {
    asm volatile("cp.async.wait_group %0;\n" :: "n"(N) : "memory");
}

__global__ __launch_bounds__(256, 2)
void proposal_kernel(const float* __restrict__ feat,
                     const float* __restrict__ Wc,
                     const float* __restrict__ bc,
                     const float* __restrict__ Wr,
                     const float* __restrict__ br,
                     float* __restrict__ out)
{
    const int tid  = threadIdx.x;
    const int lane = tid & 31;
    const int warp = tid >> 5;
    const int gid  = lane >> 2;          // 0..7
    const int tg   = lane & 3;           // 0..3

    // warp pixel window (32 px; never crosses batch: NPIX % 32 == 0)
    const int wbase = blockIdx.x * 256 + warp * 32;
    const int bw    = wbase / NPIX;
    const int pw    = wbase % NPIX;

    // warp-private staging: lane role = channel c_l (0..7) x 8-px chunk (0..3)
    const int c_l = gid;                 // channel within stage
    const int pq  = tg * 8;              // pixel offset within warp window
    float* sa_warp = s_buf + warp * SA_WARP;
    const unsigned sa_u = (unsigned)__cvta_generic_to_shared(sa_warp);
    const unsigned dst_off = (unsigned)((c_l * SA_ROW + pq) * 4);
    const float* gsrc = feat + (long)bw * CIN * NPIX + (long)c_l * NPIX + pw + pq;

    // ---- prologue: issue stages 0..6 ----
#pragma unroll
    for (int s = 0; s < RING - 1; s++) {
        const float* g = gsrc + (long)(8 * s) * NPIX;
        const unsigned d = sa_u + (unsigned)(s * SA_BUF * 4) + dst_off;
        cp16(d, g);
        cp16(d + 16, g + 4);
        cp_commit();
    }

    // ---- per-thread B-row pointers: o = 8*nt + gid ----
    const float* wrow[6];
#pragma unroll
    for (int nt = 0; nt < 6; nt++) {
        const int o = 8 * nt + gid;
        wrow[nt] = (o < 6) ? (Wc + (long)o * CIN) : (Wr + (long)(o - 6) * CIN);
    }

    // acc[mt][nt][0..3]: c0=(h0,even) c1=(h0,odd) c2=(h1,even) c3=(h1,odd); n=8*nt+2*tg(+1)
    float acc[2][6][4];
#pragma unroll
    for (int nt = 0; nt < 6; nt++) {
        const int O = 8 * nt + 2 * tg;
        const float be = (O     < 6) ? bc[O]     : br[O - 6];
        const float bo = (O + 1 < 6) ? bc[O + 1] : br[O + 1 - 6];
#pragma unroll
        for (int mt = 0; mt < 2; mt++) {
            acc[mt][nt][0] = be; acc[mt][nt][1] = bo;
            acc[mt][nt][2] = be; acc[mt][nt][3] = bo;
        }
    }

    // A-fragment offsets within a stage buffer: element (px m, chan k) at [k*SA_ROW + m]
    // pixel m = mt*16 + h*8 + gid; bank = 8*k + m (mod 32) -> conflict-free
    const int fr0 = tg * SA_ROW + gid;        // k=tg
    const int fr4 = (tg + 4) * SA_ROW + gid;  // k=tg+4

    // ---- main loop: uniform, guarded issue + empty commit keeps group algebra exact ----
#pragma unroll 2
    for (int s = 0; s < NSTAGE; s++) {
        if (s + (RING - 1) < NSTAGE) {
            const float* g = gsrc + (long)(8 * (s + RING - 1)) * NPIX;
            const unsigned d = sa_u +
                (unsigned)((((s + RING - 1) & (RING - 1)) * SA_BUF) * 4) + dst_off;
            cp16(d, g);
            cp16(d + 16, g + 4);
        }
        cp_commit();          // one group per iteration (possibly empty)
        cp_wait<6>();         // groups 0..s+1 complete => stage s ready
        __syncwarp();

        const float* sb = sa_warp + (s & (RING - 1)) * SA_BUF;
        unsigned a0[4], a1[4];
        a0[0] = __float_as_uint(to_tf32(sb[fr0 + 0]));
        a0[1] = __float_as_uint(to_tf32(sb[fr0 + 8]));
        a0[2] = __float_as_uint(to_tf32(sb[fr4 + 0]));
        a0[3] = __float_as_uint(to_tf32(sb[fr4 + 8]));
        a1[0] = __float_as_uint(to_tf32(sb[fr0 + 16]));
        a1[1] = __float_as_uint(to_tf32(sb[fr0 + 24]));
        a1[2] = __float_as_uint(to_tf32(sb[fr4 + 16]));
        a1[3] = __float_as_uint(to_tf32(sb[fr4 + 24]));

        const int k0 = 8 * s;
#pragma unroll
        for (int nt = 0; nt < 6; nt++) {
            unsigned bfr[2];
            bfr[0] = __float_as_uint(to_tf32(__ldg(wrow[nt] + k0 + tg)));      // L1-hot
            bfr[1] = __float_as_uint(to_tf32(__ldg(wrow[nt] + k0 + tg + 4)));
            mma_tf32(acc[0][nt], a0, bfr);
            mma_tf32(acc[1][nt], a1, bfr);
        }
    }

    // ================= epilogue (R6/R8/R11-validated) =================
    // pixel = pw + mt*16 + h*8 + gid; pair Q = 4*nt + tg -> outputs (2Q, 2Q+1); even->y0, odd->y1
    float* outr = out + (long)NB * 6 * NPIX;
#pragma unroll
    for (int mt = 0; mt < 2; mt++) {
#pragma unroll
        for (int h = 0; h < 2; h++) {
            const int p = pw + mt * 16 + h * 8 + gid;
#pragma unroll
            for (int nt = 0; nt < 6; nt++) {
                const float ve = acc[mt][nt][2 * h + 0];
                const float vo = acc[mt][nt][2 * h + 1];
                const int Q = 4 * nt + tg;
                if (Q < 3) {
                    out[((long)bw * 6 + 2 * Q + 0) * NPIX + p] = ve;
                    out[((long)bw * 6 + 2 * Q + 1) * NPIX + p] = vo;
                } else {
                    const int r  = Q - 3;
                    const int c3 = r / 7;
                    const int d  = r % 7;
                    outr[((((long)bw * 3 + c3) * 2 + 0) * NPIX + p) * 7 + d] = ve;
                    outr[((((long)bw * 3 + c3) * 2 + 1) * NPIX + p) * 7 + d] = vo;
                }
            }
        }
    }
}

extern "C" void kernel_launch(void* const* d_in, const int* in_sizes, int n_in,
                              void* d_out, int out_size)
{
    const float* feat = (const float*)d_in[0];
    const float* Wc   = (const float*)d_in[1];
    const float* bc   = (const float*)d_in[2];
    const float* Wr   = (const float*)d_in[3];
    const float* br   = (const float*)d_in[4];
    float* out = (float*)d_out;

    const int smem_bytes = SMEM_FLOATS * (int)sizeof(float);   // 81920 B
    cudaFuncSetAttribute(proposal_kernel,
                         cudaFuncAttributeMaxDynamicSharedMemorySize, smem_bytes);

    const int threads = 256;                 // 8 warps x 32 px
    const int blocks  = TOTAL_PIX / 256;     // 550, exact
    proposal_kernel<<<blocks, threads, smem_bytes>>>(feat, Wc, bc, Wr, br, out);
}

// round 13
// speedup vs baseline: 1.5363x; 1.5363x over previous
#include <cuda_runtime.h>

#define NOUT 48
#define CIN 384
#define NPIX 35200       // 200*176; %32==0
#define NB 4
#define TOTAL_PIX 140800 // = 550 * 256
#define NSTAGE 48        // CIN / 8
#define RING 3           // warp-private ring depth; prefetch distance 2

#define WSTR 388         // ws row stride [o][k]: 388 mod 32 = 4 -> B-frag bank 4*gid+tg (CF)
#define WS_F (NOUT * WSTR)          // 18624
#define BS_OFF WS_F
#define SA_OFF (WS_F + NOUT + 8)    // 18680 floats (16B-aligned *4)
#define SA_ROW 40                   // 32 px + pad; 40 mod 32 = 8 -> A-frag LDS CF
#define SA_BUF (8 * SA_ROW)         // 320 floats per stage buffer
#define SA_WARP (RING * SA_BUF)     // 960 floats per warp
#define SMEM_FLOATS (SA_OFF + 8 * SA_WARP)   // 26360 -> 105440 B (2 blocks/SM)

extern __shared__ float s_buf[];

__device__ __forceinline__ float to_tf32(float x) {
    float r;
    asm("cvt.rna.tf32.f32 %0, %1;" : "=f"(r) : "f"(x));
    return r;
}

__device__ __forceinline__ void mma_tf32(float c[4], const unsigned a[4], const unsigned b[2]) {
    asm("mma.sync.aligned.m16n8k8.row.col.f32.tf32.tf32.f32 "
        "{%0,%1,%2,%3}, {%4,%5,%6,%7}, {%8,%9}, {%0,%1,%2,%3};"
        : "+f"(c[0]), "+f"(c[1]), "+f"(c[2]), "+f"(c[3])
        : "r"(a[0]), "r"(a[1]), "r"(a[2]), "r"(a[3]), "r"(b[0]), "r"(b[1]));
}

__device__ __forceinline__ void cp16(unsigned sdst, const float* gsrc) {
    asm volatile("cp.async.cg.shared.global [%0], [%1], 16;\n"
                 :: "r"(sdst), "l"(gsrc) : "memory");
}
__device__ __forceinline__ void cp_commit() {
    asm volatile("cp.async.commit_group;\n" ::: "memory");
}
template <int N>
__device__ __forceinline__ void cp_wait() {
    asm volatile("cp.async.wait_group %0;\n" :: "n"(N) : "memory");
}

__global__ __launch_bounds__(256, 2)
void proposal_kernel(const float* __restrict__ feat,
                     const float* __restrict__ Wc,
                     const float* __restrict__ bc,
                     const float* __restrict__ Wr,
                     const float* __restrict__ br,
                     float* __restrict__ out)
{
    float* ws = s_buf;                   // ws[o*WSTR + k] = tf32(W[o][k])
    float* bs = s_buf + BS_OFF;

    const int tid  = threadIdx.x;
    const int lane = tid & 31;
    const int warp = tid >> 5;
    const int gid  = lane >> 2;          // 0..7
    const int tg   = lane & 3;           // 0..3

    // warp pixel window (32 px; never crosses batch: NPIX % 32 == 0)
    const int wbase = blockIdx.x * 256 + warp * 32;
    const int bw    = wbase / NPIX;
    const int pw    = wbase % NPIX;

    // warp-private staging: lane role = channel gid (0..7) x 8-px chunk tg (0..3)
    const int pq  = tg * 8;
    float* sa_warp = s_buf + SA_OFF + warp * SA_WARP;
    const unsigned sa_u = (unsigned)__cvta_generic_to_shared(sa_warp);
    const unsigned dst_off = (unsigned)((gid * SA_ROW + pq) * 4);
    const float* gsrc = feat + (long)bw * CIN * NPIX + (long)gid * NPIX + pw + pq;

    // ---- prologue: issue stages 0..1 (overlaps with weight fill) ----
#pragma unroll
    for (int s = 0; s < RING - 1; s++) {
        const float* g = gsrc + (long)(8 * s) * NPIX;
        const unsigned d = sa_u + (unsigned)(s * SA_BUF * 4) + dst_off;
        cp16(d, g);
        cp16(d + 16, g + 4);
        cp_commit();
    }

    // ---- weight + bias staging ([o][k], R11-validated) ----
    for (int i = tid; i < NOUT * CIN; i += blockDim.x) {
        const int o = i / CIN;
        const int k = i % CIN;
        ws[o * WSTR + k] = to_tf32((o < 6) ? Wc[o * CIN + k] : Wr[(o - 6) * CIN + k]);
    }
    if (tid < NOUT) bs[tid] = (tid < 6) ? bc[tid] : br[tid - 6];
    __syncthreads();   // the only block barrier in the kernel

    // acc[mt][nt][0..3]: c0=(h0,even) c1=(h0,odd) c2=(h1,even) c3=(h1,odd); n=8*nt+2*tg(+1)
    float acc[2][6][4];
#pragma unroll
    for (int nt = 0; nt < 6; nt++) {
        const float be = bs[8 * nt + 2 * tg];
        const float bo = bs[8 * nt + 2 * tg + 1];
#pragma unroll
        for (int mt = 0; mt < 2; mt++) {
            acc[mt][nt][0] = be; acc[mt][nt][1] = bo;
            acc[mt][nt][2] = be; acc[mt][nt][3] = bo;
        }
    }

    const unsigned* wsu = (const unsigned*)ws;
    // A-fragment offsets (bank = 8*k + m mod 32, conflict-free)
    const int fr0 = tg * SA_ROW + gid;        // k=tg
    const int fr4 = (tg + 4) * SA_ROW + gid;  // k=tg+4
    const int wo  = gid * WSTR;               // B row base: o = 8*nt + gid

    // ---- main loop: warp-private, barrier-free ----
    // issue-before-compute: at iter s we write buf (s+2)%3 = buf of stage s-1,
    // already consumed by THIS warp (serial compute, warp-private buffer) -> WAR-safe.
#pragma unroll 3
    for (int s = 0; s < NSTAGE; s++) {
        if (s + RING - 1 < NSTAGE) {
            const float* g = gsrc + (long)(8 * (s + RING - 1)) * NPIX;
            const unsigned d = sa_u +
                (unsigned)((((s + RING - 1) % RING) * SA_BUF) * 4) + dst_off;
            cp16(d, g);
            cp16(d + 16, g + 4);
        }
        cp_commit();          // one group per iter (possibly empty) -> exact algebra
        cp_wait<2>();         // s+3 groups committed; <=2 pending => stage s ready
        __syncwarp();

        const float* sb = sa_warp + (s % RING) * SA_BUF;
        unsigned a0[4], a1[4];
        a0[0] = __float_as_uint(to_tf32(sb[fr0 + 0]));
        a0[1] = __float_as_uint(to_tf32(sb[fr0 + 8]));
        a0[2] = __float_as_uint(to_tf32(sb[fr4 + 0]));
        a0[3] = __float_as_uint(to_tf32(sb[fr4 + 8]));
        a1[0] = __float_as_uint(to_tf32(sb[fr0 + 16]));
        a1[1] = __float_as_uint(to_tf32(sb[fr0 + 24]));
        a1[2] = __float_as_uint(to_tf32(sb[fr4 + 16]));
        a1[3] = __float_as_uint(to_tf32(sb[fr4 + 24]));

        const int k0 = 8 * s;
#pragma unroll
        for (int nt = 0; nt < 6; nt++) {
            unsigned bfr[2];
            bfr[0] = wsu[wo + nt * (8 * WSTR) + k0 + tg];       // conflict-free LDS
            bfr[1] = wsu[wo + nt * (8 * WSTR) + k0 + tg + 4];
            mma_tf32(acc[0][nt], a0, bfr);
            mma_tf32(acc[1][nt], a1, bfr);
        }
    }

    // ================= epilogue (R6/R8/R11-validated) =================
    // pixel = pw + mt*16 + h*8 + gid; pair Q = 4*nt + tg -> outputs (2Q, 2Q+1); even->y0, odd->y1
    float* outr = out + (long)NB * 6 * NPIX;
#pragma unroll
    for (int mt = 0; mt < 2; mt++) {
#pragma unroll
        for (int h = 0; h < 2; h++) {
            const int p = pw + mt * 16 + h * 8 + gid;
#pragma unroll
            for (int nt = 0; nt < 6; nt++) {
                const float ve = acc[mt][nt][2 * h + 0];
                const float vo = acc[mt][nt][2 * h + 1];
                const int Q = 4 * nt + tg;
                if (Q < 3) {
                    out[((long)bw * 6 + 2 * Q + 0) * NPIX + p] = ve;
                    out[((long)bw * 6 + 2 * Q + 1) * NPIX + p] = vo;
                } else {
                    const int r  = Q - 3;
                    const int c3 = r / 7;
                    const int d  = r % 7;
                    outr[((((long)bw * 3 + c3) * 2 + 0) * NPIX + p) * 7 + d] = ve;
                    outr[((((long)bw * 3 + c3) * 2 + 1) * NPIX + p) * 7 + d] = vo;
                }
            }
        }
    }
}

extern "C" void kernel_launch(void* const* d_in, const int* in_sizes, int n_in,
                              void* d_out, int out_size)
{
    const float* feat = (const float*)d_in[0];
    const float* Wc   = (const float*)d_in[1];
    const float* bc   = (const float*)d_in[2];
    const float* Wr   = (const float*)d_in[3];
    const float* br   = (const float*)d_in[4];
    float* out = (float*)d_out;

    const int smem_bytes = SMEM_FLOATS * (int)sizeof(float);   // 105440 B
    cudaFuncSetAttribute(proposal_kernel,
                         cudaFuncAttributeMaxDynamicSharedMemorySize, smem_bytes);

    const int threads = 256;                 // 8 warps x 32 px
    const int blocks  = TOTAL_PIX / 256;     // 550, exact
    proposal_kernel<<<blocks, threads, smem_bytes>>>(feat, Wc, bc, Wr, br, out);
}

// round 14
// speedup vs baseline: 1.7254x; 1.1231x over previous
#include <cuda_runtime.h>

#define NOUT 48
#define CIN 384
#define NPIX 35200       // 200*176; %32==0
#define NB 4
#define TOTAL_PIX 140800 // = 275 * 512
#define NSTAGE 48        // CIN / 8
#define RING 6           // warp-private ring depth; prefetch distance 5
#define NWARP 16         // 512 threads

#define WSTR 388         // ws row stride [o][k]: 388 mod 32 = 4 -> B-frag bank 4*gid+tg (CF)
#define WS_F (NOUT * WSTR)          // 18624
#define BS_OFF WS_F
#define SA_OFF (WS_F + NOUT + 8)    // 18680 floats (16B-aligned *4)
#define SA_ROW 40                   // 32 px + pad; 40 mod 32 = 8 -> A-frag LDS CF
#define SA_BUF (8 * SA_ROW)         // 320 floats per stage buffer
#define SA_WARP (RING * SA_BUF)     // 1920 floats per warp
#define SMEM_FLOATS (SA_OFF + NWARP * SA_WARP)   // 49400 -> 197600 B (1 block/SM)

extern __shared__ float s_buf[];

__device__ __forceinline__ float to_tf32(float x) {
    float r;
    asm("cvt.rna.tf32.f32 %0, %1;" : "=f"(r) : "f"(x));
    return r;
}

__device__ __forceinline__ void mma_tf32(float c[4], const unsigned a[4], const unsigned b[2]) {
    asm("mma.sync.aligned.m16n8k8.row.col.f32.tf32.tf32.f32 "
        "{%0,%1,%2,%3}, {%4,%5,%6,%7}, {%8,%9}, {%0,%1,%2,%3};"
        : "+f"(c[0]), "+f"(c[1]), "+f"(c[2]), "+f"(c[3])
        : "r"(a[0]), "r"(a[1]), "r"(a[2]), "r"(a[3]), "r"(b[0]), "r"(b[1]));
}

__device__ __forceinline__ void cp16(unsigned sdst, const float* gsrc) {
    asm volatile("cp.async.cg.shared.global [%0], [%1], 16;\n"
                 :: "r"(sdst), "l"(gsrc) : "memory");
}
__device__ __forceinline__ void cp_commit() {
    asm volatile("cp.async.commit_group;\n" ::: "memory");
}
template <int N>
__device__ __forceinline__ void cp_wait() {
    asm volatile("cp.async.wait_group %0;\n" :: "n"(N) : "memory");
}

__global__ __launch_bounds__(512, 1)
void proposal_kernel(const float* __restrict__ feat,
                     const float* __restrict__ Wc,
                     const float* __restrict__ bc,
                     const float* __restrict__ Wr,
                     const float* __restrict__ br,
                     float* __restrict__ out)
{
    float* ws = s_buf;                   // ws[o*WSTR + k] = tf32(W[o][k])
    float* bs = s_buf + BS_OFF;

    const int tid  = threadIdx.x;
    const int lane = tid & 31;
    const int warp = tid >> 5;           // 0..15
    const int gid  = lane >> 2;          // 0..7
    const int tg   = lane & 3;           // 0..3

    // warp pixel window (32 px; never crosses batch: NPIX % 32 == 0)
    const int wbase = blockIdx.x * 512 + warp * 32;
    const int bw    = wbase / NPIX;
    const int pw    = wbase % NPIX;

    // warp-private staging: lane role = channel gid (0..7) x 8-px chunk tg (0..3)
    const int pq  = tg * 8;
    float* sa_warp = s_buf + SA_OFF + warp * SA_WARP;
    const unsigned sa_u = (unsigned)__cvta_generic_to_shared(sa_warp);
    const unsigned dst_off = (unsigned)((gid * SA_ROW + pq) * 4);
    const float* gsrc = feat + (long)bw * CIN * NPIX + (long)gid * NPIX + pw + pq;

    // ---- prologue: issue stages 0..RING-2 (overlaps with weight fill) ----
#pragma unroll
    for (int s = 0; s < RING - 1; s++) {
        const float* g = gsrc + (long)(8 * s) * NPIX;
        const unsigned d = sa_u + (unsigned)(s * SA_BUF * 4) + dst_off;
        cp16(d, g);
        cp16(d + 16, g + 4);
        cp_commit();
    }

    // ---- weight + bias staging ([o][k], R11/R13-validated) ----
    for (int i = tid; i < NOUT * CIN; i += blockDim.x) {
        const int o = i / CIN;
        const int k = i % CIN;
        ws[o * WSTR + k] = to_tf32((o < 6) ? Wc[o * CIN + k] : Wr[(o - 6) * CIN + k]);
    }
    if (tid < NOUT) bs[tid] = (tid < 6) ? bc[tid] : br[tid - 6];
    __syncthreads();   // the only block barrier in the kernel

    // acc[mt][nt][0..3]: c0=(h0,even) c1=(h0,odd) c2=(h1,even) c3=(h1,odd); n=8*nt+2*tg(+1)
    float acc[2][6][4];
#pragma unroll
    for (int nt = 0; nt < 6; nt++) {
        const float be = bs[8 * nt + 2 * tg];
        const float bo = bs[8 * nt + 2 * tg + 1];
#pragma unroll
        for (int mt = 0; mt < 2; mt++) {
            acc[mt][nt][0] = be; acc[mt][nt][1] = bo;
            acc[mt][nt][2] = be; acc[mt][nt][3] = bo;
        }
    }

    const unsigned* wsu = (const unsigned*)ws;
    // A-fragment offsets (bank = 8*k + m mod 32, conflict-free)
    const int fr0 = tg * SA_ROW + gid;        // k=tg
    const int fr4 = (tg + 4) * SA_ROW + gid;  // k=tg+4
    const int wo  = gid * WSTR;               // B row base: o = 8*nt + gid

    // ---- main loop: warp-private, barrier-free (R13-validated scheme, ring 6) ----
    // WAR: writing buf (s+RING-1)%RING = (s-1)%RING, already consumed by THIS warp.
#pragma unroll 6
    for (int s = 0; s < NSTAGE; s++) {
        if (s + RING - 1 < NSTAGE) {
            const float* g = gsrc + (long)(8 * (s + RING - 1)) * NPIX;
            const unsigned d = sa_u +
                (unsigned)((((s + RING - 1) % RING) * SA_BUF) * 4) + dst_off;
            cp16(d, g);
            cp16(d + 16, g + 4);
        }
        cp_commit();            // one group per iter (possibly empty) -> exact algebra
        cp_wait<RING - 2>();    // s+RING committed; <=RING-2 pending => stage s ready
        __syncwarp();

        const float* sb = sa_warp + (s % RING) * SA_BUF;
        unsigned a0[4], a1[4];
        a0[0] = __float_as_uint(to_tf32(sb[fr0 + 0]));
        a0[1] = __float_as_uint(to_tf32(sb[fr0 + 8]));
        a0[2] = __float_as_uint(to_tf32(sb[fr4 + 0]));
        a0[3] = __float_as_uint(to_tf32(sb[fr4 + 8]));
        a1[0] = __float_as_uint(to_tf32(sb[fr0 + 16]));
        a1[1] = __float_as_uint(to_tf32(sb[fr0 + 24]));
        a1[2] = __float_as_uint(to_tf32(sb[fr4 + 16]));
        a1[3] = __float_as_uint(to_tf32(sb[fr4 + 24]));

        const int k0 = 8 * s;
#pragma unroll
        for (int nt = 0; nt < 6; nt++) {
            unsigned bfr[2];
            bfr[0] = wsu[wo + nt * (8 * WSTR) + k0 + tg];       // conflict-free LDS
            bfr[1] = wsu[wo + nt * (8 * WSTR) + k0 + tg + 4];
            mma_tf32(acc[0][nt], a0, bfr);
            mma_tf32(acc[1][nt], a1, bfr);
        }
    }

    // ================= epilogue (validated since R6) =================
    // pixel = pw + mt*16 + h*8 + gid; pair Q = 4*nt + tg -> outputs (2Q, 2Q+1); even->y0, odd->y1
    float* outr = out + (long)NB * 6 * NPIX;
#pragma unroll
    for (int mt = 0; mt < 2; mt++) {
#pragma unroll
        for (int h = 0; h < 2; h++) {
            const int p = pw + mt * 16 + h * 8 + gid;
#pragma unroll
            for (int nt = 0; nt < 6; nt++) {
                const float ve = acc[mt][nt][2 * h + 0];
                const float vo = acc[mt][nt][2 * h + 1];
                const int Q = 4 * nt + tg;
                if (Q < 3) {
                    out[((long)bw * 6 + 2 * Q + 0) * NPIX + p] = ve;
                    out[((long)bw * 6 + 2 * Q + 1) * NPIX + p] = vo;
                } else {
                    const int r  = Q - 3;
                    const int c3 = r / 7;
                    const int d  = r % 7;
                    outr[((((long)bw * 3 + c3) * 2 + 0) * NPIX + p) * 7 + d] = ve;
                    outr[((((long)bw * 3 + c3) * 2 + 1) * NPIX + p) * 7 + d] = vo;
                }
            }
        }
    }
}

extern "C" void kernel_launch(void* const* d_in, const int* in_sizes, int n_in,
                              void* d_out, int out_size)
{
    const float* feat = (const float*)d_in[0];
    const float* Wc   = (const float*)d_in[1];
    const float* bc   = (const float*)d_in[2];
    const float* Wr   = (const float*)d_in[3];
    const float* br   = (const float*)d_in[4];
    float* out = (float*)d_out;

    const int smem_bytes = SMEM_FLOATS * (int)sizeof(float);   // 197600 B
    cudaFuncSetAttribute(proposal_kernel,
                         cudaFuncAttributeMaxDynamicSharedMemorySize, smem_bytes);

    const int threads = 512;                 // 16 warps x 32 px = 512 px/block
    const int blocks  = TOTAL_PIX / 512;     // 275, exact
    proposal_kernel<<<blocks, threads, smem_bytes>>>(feat, Wc, bc, Wr, br, out);
}